// round 1
// baseline (speedup 1.0000x reference)
#include <cuda_runtime.h>

// ---------------- problem constants ----------------
#define BB   4
#define LL   2048
#define DM   1024
#define DI   2048      // d_inner
#define DS   16        // d_state
#define DTR  64        // dt_rank
#define NP   96        // dt_rank + 2*d_state
#define BL   (BB*LL)   // 8192 rows

// ---------------- scratch (static device globals; no runtime alloc) ----------------
__device__ float g_xn   [BL*DM];      // layernorm output
__device__ float g_xz   [BL*2*DI];    // in_proj output [xi | z]
__device__ float g_xi   [BL*DI];      // post conv+silu
__device__ float g_proj [BL*NP];      // xproj output [dt | B | C]
__device__ float g_delta[BL*DI];      // softplus(dt @ dt_w.T + dt_b)
__device__ float g_ycore[BL*DI];      // scan output * silu(z)
__device__ float g_ycat [BL*2*DM];    // [y_f | y_b] for merge

// ---------------- helpers ----------------
__device__ __forceinline__ float sigmoidf_(float x) {
    return 1.f / (1.f + __expf(-x));
}
__device__ __forceinline__ float softplusf_(float x) {
    return (x > 20.f) ? x : log1pf(__expf(x));
}

// ---------------- LayerNorm: one block per row of 1024 ----------------
__global__ void __launch_bounds__(256) ln_kernel(
    const float* __restrict__ x, const float* __restrict__ g,
    const float* __restrict__ b)
{
    int row = blockIdx.x;
    const float4* xr = reinterpret_cast<const float4*>(x + (size_t)row * DM);
    float4 v = xr[threadIdx.x];
    float s  = v.x + v.y + v.z + v.w;
    float ss = v.x*v.x + v.y*v.y + v.z*v.z + v.w*v.w;
    // warp reduce
    #pragma unroll
    for (int o = 16; o; o >>= 1) {
        s  += __shfl_xor_sync(0xffffffffu, s,  o);
        ss += __shfl_xor_sync(0xffffffffu, ss, o);
    }
    __shared__ float sh[8], sh2[8];
    int wid = threadIdx.x >> 5, lane = threadIdx.x & 31;
    if (lane == 0) { sh[wid] = s; sh2[wid] = ss; }
    __syncthreads();
    float S = 0.f, SS = 0.f;
    #pragma unroll
    for (int i = 0; i < 8; i++) { S += sh[i]; SS += sh2[i]; }
    float mu  = S * (1.f / DM);
    float var = SS * (1.f / DM) - mu * mu;
    float inv = rsqrtf(var + 1e-5f);
    const float4* gv4 = reinterpret_cast<const float4*>(g);
    const float4* bv4 = reinterpret_cast<const float4*>(b);
    float4 gv = gv4[threadIdx.x], bv = bv4[threadIdx.x];
    float4 o4;
    o4.x = (v.x - mu) * inv * gv.x + bv.x;
    o4.y = (v.y - mu) * inv * gv.y + bv.y;
    o4.z = (v.z - mu) * inv * gv.z + bv.z;
    o4.w = (v.w - mu) * inv * gv.w + bv.w;
    reinterpret_cast<float4*>(g_xn + (size_t)row * DM)[threadIdx.x] = o4;
}

// ---------------- generic fp32 tiled GEMM: C = act(A @ W^T + bias) (+ resid) ----------------
// A [M, lda-major], W [N, K] row-major (weight layout), C [M, ldc].
// M is implied by gridDim.y*128 (always 8192 here). K % 16 == 0.
// act: 0 = none, 1 = softplus
__global__ void __launch_bounds__(256) gemm_kernel(
    const float* __restrict__ A, int lda,
    const float* __restrict__ W, int ldw,
    float* __restrict__ C, int ldc,
    int N, int K,
    const float* __restrict__ bias,
    const float* __restrict__ resid, int ldr,
    int act)
{
    __shared__ float As[16][132];
    __shared__ float Bs[16][132];

    const int tid = threadIdx.x;
    const int tx = tid & 15, ty = tid >> 4;
    const int m0 = blockIdx.y * 128, n0 = blockIdx.x * 128;

    float acc[8][8];
    #pragma unroll
    for (int i = 0; i < 8; i++)
        #pragma unroll
        for (int j = 0; j < 8; j++) acc[i][j] = 0.f;

    for (int k0 = 0; k0 < K; k0 += 16) {
        // load A tile (128x16) transposed into As[k][m]
        #pragma unroll
        for (int r = 0; r < 2; r++) {
            int s  = tid + r * 256;
            int mm = s >> 2;
            int kq = (s & 3) * 4;
            float4 v = *reinterpret_cast<const float4*>(
                &A[(size_t)(m0 + mm) * lda + k0 + kq]);
            As[kq + 0][mm] = v.x; As[kq + 1][mm] = v.y;
            As[kq + 2][mm] = v.z; As[kq + 3][mm] = v.w;
        }
        // load W tile (128x16) transposed into Bs[k][n]
        #pragma unroll
        for (int r = 0; r < 2; r++) {
            int s  = tid + r * 256;
            int nn = s >> 2;
            int kq = (s & 3) * 4;
            float4 v = make_float4(0.f, 0.f, 0.f, 0.f);
            if (n0 + nn < N)
                v = *reinterpret_cast<const float4*>(
                    &W[(size_t)(n0 + nn) * ldw + k0 + kq]);
            Bs[kq + 0][nn] = v.x; Bs[kq + 1][nn] = v.y;
            Bs[kq + 2][nn] = v.z; Bs[kq + 3][nn] = v.w;
        }
        __syncthreads();

        #pragma unroll
        for (int kk = 0; kk < 16; kk++) {
            float af[8], bf[8];
            *reinterpret_cast<float4*>(af)     = *reinterpret_cast<const float4*>(&As[kk][ty * 8]);
            *reinterpret_cast<float4*>(af + 4) = *reinterpret_cast<const float4*>(&As[kk][ty * 8 + 4]);
            *reinterpret_cast<float4*>(bf)     = *reinterpret_cast<const float4*>(&Bs[kk][tx * 8]);
            *reinterpret_cast<float4*>(bf + 4) = *reinterpret_cast<const float4*>(&Bs[kk][tx * 8 + 4]);
            #pragma unroll
            for (int i = 0; i < 8; i++)
                #pragma unroll
                for (int j = 0; j < 8; j++)
                    acc[i][j] += af[i] * bf[j];
        }
        __syncthreads();
    }

    // epilogue
    #pragma unroll
    for (int i = 0; i < 8; i++) {
        int m = m0 + ty * 8 + i;
        #pragma unroll
        for (int j = 0; j < 8; j++) {
            int n = n0 + tx * 8 + j;
            if (n < N) {
                float v = acc[i][j];
                if (bias)  v += bias[n];
                if (act == 1) v = softplusf_(v);
                if (resid) v += resid[(size_t)m * ldr + n];
                C[(size_t)m * ldc + n] = v;
            }
        }
    }
}

// ---------------- depthwise causal conv (len 4) + silu ----------------
// fwd: taps x[t-3+j] (j=0..3). bwd (flipped seq, written back at original
// positions): taps x[t+3-j]. Input is first DI columns of g_xz.
__global__ void conv_silu_kernel(const float* __restrict__ cw,
                                 const float* __restrict__ cb, int dir)
{
    int idx = blockIdx.x * 256 + threadIdx.x;      // over BL*DI = 16.8M
    int d = idx & (DI - 1);
    int t = (idx >> 11) & (LL - 1);
    int b = idx >> 22;
    float acc = cb[d];
    #pragma unroll
    for (int j = 0; j < 4; j++) {
        int tt = dir ? (t + 3 - j) : (t - 3 + j);
        if ((unsigned)tt < LL)
            acc += cw[d * 4 + j] * g_xz[(size_t)((b << 11) + tt) * (2 * DI) + d];
    }
    g_xi[idx] = acc * sigmoidf_(acc);
}

// ---------------- selective scan ----------------
// 4 lanes per channel (4 states each). Block: 128 threads = 32 channels.
// grid = (DI/32, B). B/C staged through smem in chunks of 64 timesteps.
#define SCAN_TC 64
__global__ void __launch_bounds__(128) scan_kernel(
    const float* __restrict__ A_log, const float* __restrict__ Dvec, int dir)
{
    __shared__ float sBC[SCAN_TC][32];   // [t][0..15]=B, [16..31]=C

    const int lane = threadIdx.x & 31;
    const int warp = threadIdx.x >> 5;
    const int sgrp = lane & 3;                     // state group: s = sgrp*4+i
    const int d = blockIdx.x * 32 + warp * 8 + (lane >> 2);
    const int b = blockIdx.y;
    const int rowbase = b * LL;

    float Aarr[4];
    #pragma unroll
    for (int i = 0; i < 4; i++)
        Aarr[i] = -__expf(A_log[d * DS + sgrp * 4 + i]);
    const float Dd = Dvec[d];

    float h[4] = {0.f, 0.f, 0.f, 0.f};

    for (int tc = 0; tc < LL; tc += SCAN_TC) {
        __syncthreads();   // protect previous chunk's reads
        for (int k = threadIdx.x; k < SCAN_TC * 32; k += 128) {
            int t = k >> 5, c = k & 31;
            int ts = tc + t;
            int o = dir ? (LL - 1 - ts) : ts;
            sBC[t][c] = g_proj[(size_t)(rowbase + o) * NP + 64 + c];
        }
        __syncthreads();

        for (int t = 0; t < SCAN_TC; t++) {
            int ts = tc + t;
            int o = dir ? (LL - 1 - ts) : ts;
            size_t row = (size_t)(rowbase + o);
            float dlt = g_delta[row * DI + d];
            float u   = g_xi[row * DI + d];
            float du  = dlt * u;
            float y = 0.f;
            #pragma unroll
            for (int i = 0; i < 4; i++) {
                int s = sgrp * 4 + i;
                float a = __expf(dlt * Aarr[i]);
                h[i] = a * h[i] + du * sBC[t][s];
                y += h[i] * sBC[t][16 + s];
            }
            y += __shfl_xor_sync(0xffffffffu, y, 1);
            y += __shfl_xor_sync(0xffffffffu, y, 2);
            if (sgrp == 0) {
                float z = g_xz[row * (2 * DI) + DI + d];
                g_ycore[row * DI + d] = (y + u * Dd) * z * sigmoidf_(z);
            }
        }
    }
}

// ---------------- launch ----------------
extern "C" void kernel_launch(void* const* d_in, const int* in_sizes, int n_in,
                              void* d_out, int out_size)
{
    (void)in_sizes; (void)n_in; (void)out_size;

    const float* x       = (const float*)d_in[0];
    const float* ln_g    = (const float*)d_in[1];
    const float* ln_b    = (const float*)d_in[2];
    const float* merge_w = (const float*)d_in[3];
    const float* merge_b = (const float*)d_in[4];

    float *p_xn, *p_xz, *p_xi, *p_proj, *p_delta, *p_ycore, *p_ycat;
    cudaGetSymbolAddress((void**)&p_xn,    g_xn);
    cudaGetSymbolAddress((void**)&p_xz,    g_xz);
    cudaGetSymbolAddress((void**)&p_xi,    g_xi);
    cudaGetSymbolAddress((void**)&p_proj,  g_proj);
    cudaGetSymbolAddress((void**)&p_delta, g_delta);
    cudaGetSymbolAddress((void**)&p_ycore, g_ycore);
    cudaGetSymbolAddress((void**)&p_ycat,  g_ycat);

    ln_kernel<<<BL, 256>>>(x, ln_g, ln_b);

    for (int dir = 0; dir < 2; dir++) {
        int base = 5 + dir * 9;
        const float* in_w    = (const float*)d_in[base + 0];
        const float* conv_w  = (const float*)d_in[base + 1];
        const float* conv_b  = (const float*)d_in[base + 2];
        const float* xproj_w = (const float*)d_in[base + 3];
        const float* dt_w    = (const float*)d_in[base + 4];
        const float* dt_b    = (const float*)d_in[base + 5];
        const float* A_log   = (const float*)d_in[base + 6];
        const float* Dv      = (const float*)d_in[base + 7];
        const float* out_w   = (const float*)d_in[base + 8];

        // xz = xn @ in_w^T   [8192,1024]x[4096,1024]^T
        gemm_kernel<<<dim3(2 * DI / 128, BL / 128), 256>>>(
            p_xn, DM, in_w, DM, p_xz, 2 * DI, 2 * DI, DM,
            nullptr, nullptr, 0, 0);

        // xi = silu(causal_conv(xz[:, :DI]))
        conv_silu_kernel<<<(BL * DI) / 256, 256>>>(conv_w, conv_b, dir);

        // proj = xi @ xproj_w^T   [8192,2048]x[96,2048]^T
        gemm_kernel<<<dim3(1, BL / 128), 256>>>(
            p_xi, DI, xproj_w, DI, p_proj, NP, NP, DI,
            nullptr, nullptr, 0, 0);

        // delta = softplus(proj[:, :64] @ dt_w^T + dt_b)
        gemm_kernel<<<dim3(DI / 128, BL / 128), 256>>>(
            p_proj, NP, dt_w, DTR, p_delta, DI, DI, DTR,
            dt_b, nullptr, 0, 1);

        // selective scan -> ycore (gated by silu(z))
        scan_kernel<<<dim3(DI / 32, BB), 128>>>(A_log, Dv, dir);

        // y_dir = ycore @ out_w^T, written into ycat[:, dir*DM : dir*DM+DM]
        gemm_kernel<<<dim3(DM / 128, BL / 128), 256>>>(
            p_ycore, DI, out_w, DI, p_ycat + dir * DM, 2 * DM, DM, DI,
            nullptr, nullptr, 0, 0);
    }

    // out = x + ycat @ merge_w^T + merge_b
    gemm_kernel<<<dim3(DM / 128, BL / 128), 256>>>(
        p_ycat, 2 * DM, merge_w, 2 * DM, (float*)d_out, DM, DM, 2 * DM,
        merge_b, x, DM, 0);
}

// round 2
// speedup vs baseline: 1.7743x; 1.7743x over previous
#include <cuda_runtime.h>
#include <cstdint>

// ---------------- problem constants ----------------
#define BB   4
#define LL   2048
#define DM   1024
#define DI   2048      // d_inner
#define DS   16        // d_state
#define DTR  64        // dt_rank
#define NP   96        // dt_rank + 2*d_state
#define BL   (BB*LL)   // 8192 rows

// ---------------- scratch (static device globals; no runtime alloc) ----------------
__device__ float g_xn   [BL*DM];
__device__ float g_xz   [(size_t)BL*2*DI];
__device__ float g_xi   [(size_t)BL*DI];
__device__ float g_proj [BL*NP];
__device__ float g_delta[(size_t)BL*DI];
__device__ float g_ycore[(size_t)BL*DI];
__device__ float g_ycat [(size_t)BL*2*DM];

// ---------------- helpers ----------------
__device__ __forceinline__ float sigmoidf_(float x) {
    return 1.f / (1.f + __expf(-x));
}
__device__ __forceinline__ float softplusf_(float x) {
    return (x > 20.f) ? x : log1pf(__expf(x));
}
__device__ __forceinline__ uint32_t f2tf(float x) {
    uint32_t r;
    asm("cvt.rna.tf32.f32 %0, %1;" : "=r"(r) : "f"(x));
    return r;
}
__device__ __forceinline__ void mma_tf32(float* d, const uint32_t* a, const uint32_t* b) {
    asm volatile(
        "mma.sync.aligned.m16n8k8.row.col.f32.tf32.tf32.f32 "
        "{%0,%1,%2,%3}, {%4,%5,%6,%7}, {%8,%9}, {%0,%1,%2,%3};"
        : "+f"(d[0]), "+f"(d[1]), "+f"(d[2]), "+f"(d[3])
        : "r"(a[0]), "r"(a[1]), "r"(a[2]), "r"(a[3]),
          "r"(b[0]), "r"(b[1]));
}

// ---------------- LayerNorm: one block per row of 1024 ----------------
__global__ void __launch_bounds__(256) ln_kernel(
    const float* __restrict__ x, const float* __restrict__ g,
    const float* __restrict__ b)
{
    int row = blockIdx.x;
    const float4* xr = reinterpret_cast<const float4*>(x + (size_t)row * DM);
    float4 v = xr[threadIdx.x];
    float s  = v.x + v.y + v.z + v.w;
    float ss = v.x*v.x + v.y*v.y + v.z*v.z + v.w*v.w;
    #pragma unroll
    for (int o = 16; o; o >>= 1) {
        s  += __shfl_xor_sync(0xffffffffu, s,  o);
        ss += __shfl_xor_sync(0xffffffffu, ss, o);
    }
    __shared__ float sh[8], sh2[8];
    int wid = threadIdx.x >> 5, lane = threadIdx.x & 31;
    if (lane == 0) { sh[wid] = s; sh2[wid] = ss; }
    __syncthreads();
    float S = 0.f, SS = 0.f;
    #pragma unroll
    for (int i = 0; i < 8; i++) { S += sh[i]; SS += sh2[i]; }
    float mu  = S * (1.f / DM);
    float var = SS * (1.f / DM) - mu * mu;
    float inv = rsqrtf(var + 1e-5f);
    const float4* gv4 = reinterpret_cast<const float4*>(g);
    const float4* bv4 = reinterpret_cast<const float4*>(b);
    float4 gv = gv4[threadIdx.x], bv = bv4[threadIdx.x];
    float4 o4;
    o4.x = (v.x - mu) * inv * gv.x + bv.x;
    o4.y = (v.y - mu) * inv * gv.y + bv.y;
    o4.z = (v.z - mu) * inv * gv.z + bv.z;
    o4.w = (v.w - mu) * inv * gv.w + bv.w;
    reinterpret_cast<float4*>(g_xn + (size_t)row * DM)[threadIdx.x] = o4;
}

// ---------------- tf32 tensor-core GEMM: C = act(A @ W^T + bias) (+resid) ----------------
// A [M, lda], W [N, K] row-major, C [M, ldc]. M = gridDim.y*128 (8192).
// K % 32 == 0. Block 128x128, Ktile 32, 3-stage cp.async pipeline.
// Smem per tile: [128][32] fp32 with 16B-chunk XOR swizzle:
//   word(r, c) = r*32 + ((c>>2) ^ (r&7))*4 + (c&3)
#define STAGES 3
#define KT 32

__global__ void __launch_bounds__(256, 1) gemm_tc(
    const float* __restrict__ A, int lda,
    const float* __restrict__ W, int ldw,
    float* __restrict__ C, int ldc,
    int N, int K,
    const float* __restrict__ bias,
    const float* __restrict__ resid, int ldr,
    int act)
{
    extern __shared__ float smbuf[];
    float* As = smbuf;                    // STAGES * 4096 floats
    float* Bs = smbuf + STAGES * 4096;

    const int tid  = threadIdx.x;
    const int wid  = tid >> 5, lane = tid & 31;
    const int g    = lane >> 2, t4 = lane & 3;
    const int wm   = wid & 3,  wn  = wid >> 2;    // 4(m) x 2(n) warps
    const int m0   = blockIdx.y * 128, n0 = blockIdx.x * 128;

    const int lr = tid >> 3;      // loader row 0..31
    const int lq = tid & 7;       // loader 16B chunk 0..7

    const float* Abase = A + (size_t)m0 * lda;

    auto load_tile = [&](int stage, int kt) {
        const int kbase = kt * KT + lq * 4;
        float* as = As + stage * 4096;
        float* bs = Bs + stage * 4096;
        #pragma unroll
        for (int i = 0; i < 4; i++) {
            int r = lr + i * 32;
            uint32_t so = (uint32_t)__cvta_generic_to_shared(
                &as[r * 32 + ((lq ^ (r & 7)) << 2)]);
            const float* gp = Abase + (size_t)r * lda + kbase;
            asm volatile("cp.async.cg.shared.global [%0], [%1], 16;\n"
                         :: "r"(so), "l"(gp));
        }
        #pragma unroll
        for (int i = 0; i < 4; i++) {
            int r = lr + i * 32;
            int nrow = n0 + r;
            uint32_t so = (uint32_t)__cvta_generic_to_shared(
                &bs[r * 32 + ((lq ^ (r & 7)) << 2)]);
            const float* gp = W + (size_t)nrow * ldw + kbase;
            int sz = (nrow < N) ? 16 : 0;   // zero-fill OOB rows
            asm volatile("cp.async.cg.shared.global [%0], [%1], 16, %2;\n"
                         :: "r"(so), "l"(gp), "r"(sz));
        }
    };

    float acc[2][8][4];
    #pragma unroll
    for (int mi = 0; mi < 2; mi++)
        #pragma unroll
        for (int ni = 0; ni < 8; ni++)
            #pragma unroll
            for (int j = 0; j < 4; j++) acc[mi][ni][j] = 0.f;

    const int ktiles = K / KT;

    #pragma unroll
    for (int s = 0; s < STAGES - 1; s++) {
        if (s < ktiles) load_tile(s, s);
        asm volatile("cp.async.commit_group;\n");
    }
    asm volatile("cp.async.wait_group %0;\n" :: "n"(STAGES - 2));
    __syncthreads();

    // per-lane invariant word offsets (row term folded; r&7 == g everywhere)
    const int aRow = (wm * 32 + g) * 32 + t4;   // + mi*512, +256 for row+8
    const int bRow = (wn * 64 + g) * 32 + t4;   // + ni*256

    for (int kt = 0; kt < ktiles; kt++) {
        int pre = kt + STAGES - 1;
        if (pre < ktiles) load_tile(pre % STAGES, pre);
        asm volatile("cp.async.commit_group;\n");

        const float* as = As + (kt % STAGES) * 4096;
        const float* bs = Bs + (kt % STAGES) * 4096;
        #pragma unroll
        for (int kk = 0; kk < 4; kk++) {
            const int x0 = ((kk * 2) ^ g) << 2;
            const int x1 = ((kk * 2 + 1) ^ g) << 2;
            uint32_t afr[2][4];
            #pragma unroll
            for (int mi = 0; mi < 2; mi++) {
                const float* ap = as + aRow + mi * 512;
                afr[mi][0] = f2tf(ap[x0]);
                afr[mi][1] = f2tf(ap[256 + x0]);
                afr[mi][2] = f2tf(ap[x1]);
                afr[mi][3] = f2tf(ap[256 + x1]);
            }
            #pragma unroll
            for (int ni = 0; ni < 8; ni++) {
                const float* bp = bs + bRow + ni * 256;
                uint32_t bfr[2];
                bfr[0] = f2tf(bp[x0]);
                bfr[1] = f2tf(bp[x1]);
                mma_tf32(acc[0][ni], afr[0], bfr);
                mma_tf32(acc[1][ni], afr[1], bfr);
            }
        }
        asm volatile("cp.async.wait_group %0;\n" :: "n"(STAGES - 2));
        __syncthreads();
    }

    // epilogue: c0=(g,2t4) c1=(g,2t4+1) c2=(g+8,2t4) c3=(g+8,2t4+1)
    #pragma unroll
    for (int mi = 0; mi < 2; mi++) {
        int m = m0 + wm * 32 + mi * 16 + g;
        #pragma unroll
        for (int ni = 0; ni < 8; ni++) {
            int n = n0 + wn * 64 + ni * 8 + t4 * 2;
            if (n < N) {
                float v00 = acc[mi][ni][0], v01 = acc[mi][ni][1];
                float v10 = acc[mi][ni][2], v11 = acc[mi][ni][3];
                if (bias) {
                    float b0 = bias[n], b1 = bias[n + 1];
                    v00 += b0; v01 += b1; v10 += b0; v11 += b1;
                }
                if (act == 1) {
                    v00 = softplusf_(v00); v01 = softplusf_(v01);
                    v10 = softplusf_(v10); v11 = softplusf_(v11);
                }
                if (resid) {
                    v00 += resid[(size_t)m * ldr + n];
                    v01 += resid[(size_t)m * ldr + n + 1];
                    v10 += resid[(size_t)(m + 8) * ldr + n];
                    v11 += resid[(size_t)(m + 8) * ldr + n + 1];
                }
                *reinterpret_cast<float2*>(&C[(size_t)m * ldc + n]) =
                    make_float2(v00, v01);
                *reinterpret_cast<float2*>(&C[(size_t)(m + 8) * ldc + n]) =
                    make_float2(v10, v11);
            }
        }
    }
}

// ---------------- depthwise causal conv (len 4) + silu ----------------
__global__ void conv_silu_kernel(const float* __restrict__ cw,
                                 const float* __restrict__ cb, int dir)
{
    int idx = blockIdx.x * 256 + threadIdx.x;      // over BL*DI
    int d = idx & (DI - 1);
    int t = (idx >> 11) & (LL - 1);
    int b = idx >> 22;
    float acc = cb[d];
    #pragma unroll
    for (int j = 0; j < 4; j++) {
        int tt = dir ? (t + 3 - j) : (t - 3 + j);
        if ((unsigned)tt < LL)
            acc += cw[d * 4 + j] * g_xz[(size_t)((b << 11) + tt) * (2 * DI) + d];
    }
    g_xi[idx] = acc * sigmoidf_(acc);
}

// ---------------- selective scan ----------------
#define SCAN_TC 64
__global__ void __launch_bounds__(128) scan_kernel(
    const float* __restrict__ A_log, const float* __restrict__ Dvec, int dir)
{
    __shared__ float sBC[SCAN_TC][32];   // [t][0..15]=B, [16..31]=C

    const int lane = threadIdx.x & 31;
    const int warp = threadIdx.x >> 5;
    const int sgrp = lane & 3;
    const int d = blockIdx.x * 32 + warp * 8 + (lane >> 2);
    const int b = blockIdx.y;
    const int rowbase = b * LL;

    float Aarr[4];
    #pragma unroll
    for (int i = 0; i < 4; i++)
        Aarr[i] = -__expf(A_log[d * DS + sgrp * 4 + i]);
    const float Dd = Dvec[d];

    float h[4] = {0.f, 0.f, 0.f, 0.f};

    for (int tc = 0; tc < LL; tc += SCAN_TC) {
        __syncthreads();
        for (int k = threadIdx.x; k < SCAN_TC * 32; k += 128) {
            int t = k >> 5, c = k & 31;
            int ts = tc + t;
            int o = dir ? (LL - 1 - ts) : ts;
            sBC[t][c] = g_proj[(size_t)(rowbase + o) * NP + 64 + c];
        }
        __syncthreads();

        for (int t = 0; t < SCAN_TC; t++) {
            int ts = tc + t;
            int o = dir ? (LL - 1 - ts) : ts;
            size_t row = (size_t)(rowbase + o);
            float dlt = g_delta[row * DI + d];
            float u   = g_xi[row * DI + d];
            float du  = dlt * u;
            float y = 0.f;
            #pragma unroll
            for (int i = 0; i < 4; i++) {
                int s = sgrp * 4 + i;
                float a = __expf(dlt * Aarr[i]);
                h[i] = a * h[i] + du * sBC[t][s];
                y += h[i] * sBC[t][16 + s];
            }
            y += __shfl_xor_sync(0xffffffffu, y, 1);
            y += __shfl_xor_sync(0xffffffffu, y, 2);
            if (sgrp == 0) {
                float z = g_xz[row * (2 * DI) + DI + d];
                g_ycore[row * DI + d] = (y + u * Dd) * z * sigmoidf_(z);
            }
        }
    }
}

// ---------------- launch ----------------
extern "C" void kernel_launch(void* const* d_in, const int* in_sizes, int n_in,
                              void* d_out, int out_size)
{
    (void)in_sizes; (void)n_in; (void)out_size;

    const float* x       = (const float*)d_in[0];
    const float* ln_g    = (const float*)d_in[1];
    const float* ln_b    = (const float*)d_in[2];
    const float* merge_w = (const float*)d_in[3];
    const float* merge_b = (const float*)d_in[4];

    float *p_xn, *p_xz, *p_xi, *p_proj, *p_delta, *p_ycore, *p_ycat;
    cudaGetSymbolAddress((void**)&p_xn,    g_xn);
    cudaGetSymbolAddress((void**)&p_xz,    g_xz);
    cudaGetSymbolAddress((void**)&p_xi,    g_xi);
    cudaGetSymbolAddress((void**)&p_proj,  g_proj);
    cudaGetSymbolAddress((void**)&p_delta, g_delta);
    cudaGetSymbolAddress((void**)&p_ycore, g_ycore);
    cudaGetSymbolAddress((void**)&p_ycat,  g_ycat);

    const int smem = STAGES * 2 * 4096 * sizeof(float);   // 96 KB
    cudaFuncSetAttribute(gemm_tc, cudaFuncAttributeMaxDynamicSharedMemorySize, smem);

    ln_kernel<<<BL, 256>>>(x, ln_g, ln_b);

    for (int dir = 0; dir < 2; dir++) {
        int base = 5 + dir * 9;
        const float* in_w    = (const float*)d_in[base + 0];
        const float* conv_w  = (const float*)d_in[base + 1];
        const float* conv_b  = (const float*)d_in[base + 2];
        const float* xproj_w = (const float*)d_in[base + 3];
        const float* dt_w    = (const float*)d_in[base + 4];
        const float* dt_b    = (const float*)d_in[base + 5];
        const float* A_log   = (const float*)d_in[base + 6];
        const float* Dv      = (const float*)d_in[base + 7];
        const float* out_w   = (const float*)d_in[base + 8];

        // xz = xn @ in_w^T   [8192,1024] x [4096,1024]^T
        gemm_tc<<<dim3(2 * DI / 128, BL / 128), 256, smem>>>(
            p_xn, DM, in_w, DM, p_xz, 2 * DI, 2 * DI, DM,
            nullptr, nullptr, 0, 0);

        // xi = silu(causal_conv(xz[:, :DI]))
        conv_silu_kernel<<<(BL * DI) / 256, 256>>>(conv_w, conv_b, dir);

        // proj = xi @ xproj_w^T   [8192,2048] x [96,2048]^T
        gemm_tc<<<dim3(1, BL / 128), 256, smem>>>(
            p_xi, DI, xproj_w, DI, p_proj, NP, NP, DI,
            nullptr, nullptr, 0, 0);

        // delta = softplus(proj[:, :64] @ dt_w^T + dt_b)
        gemm_tc<<<dim3(DI / 128, BL / 128), 256, smem>>>(
            p_proj, NP, dt_w, DTR, p_delta, DI, DI, DTR,
            dt_b, nullptr, 0, 1);

        // selective scan -> ycore (gated by silu(z))
        scan_kernel<<<dim3(DI / 32, BB), 128>>>(A_log, Dv, dir);

        // y_dir = ycore @ out_w^T into ycat[:, dir*DM:]
        gemm_tc<<<dim3(DM / 128, BL / 128), 256, smem>>>(
            p_ycore, DI, out_w, DI, p_ycat + dir * DM, 2 * DM, DM, DI,
            nullptr, nullptr, 0, 0);
    }

    // out = x + ycat @ merge_w^T + merge_b
    gemm_tc<<<dim3(DM / 128, BL / 128), 256, smem>>>(
        p_ycat, 2 * DM, merge_w, 2 * DM, (float*)d_out, DM, DM, 2 * DM,
        merge_b, x, DM, 0);
}

// round 3
// speedup vs baseline: 1.8559x; 1.0460x over previous
#include <cuda_runtime.h>
#include <cstdint>

// ---------------- problem constants ----------------
#define BB   4
#define LL   2048
#define DM   1024
#define DI   2048      // d_inner
#define DS   16        // d_state
#define DTR  64        // dt_rank
#define NP   96        // dt_rank + 2*d_state
#define BL   (BB*LL)   // 8192 rows

// ---------------- scratch (static device globals; no runtime alloc) ----------------
__device__ float g_xn   [BL*DM];
__device__ float g_xz   [(size_t)BL*2*DI];
__device__ float g_xi   [(size_t)BL*DI];
__device__ float g_proj [BL*NP];
__device__ float g_delta[(size_t)BL*DI];
__device__ float g_ycore[(size_t)BL*DI];
__device__ float g_ycat [(size_t)BL*2*DM];
// tf32-rounded weight copies (reused across directions; stream order = safe)
__device__ float w_in [2*DI*DM];     // 4096 x 1024
__device__ float w_xp [NP*DI];
__device__ float w_dt [DI*DTR];
__device__ float w_out[DM*DI];
__device__ float w_mg [DM*2*DM];

// ---------------- helpers ----------------
__device__ __forceinline__ float sigmoidf_(float x) {
    return 1.f / (1.f + __expf(-x));
}
__device__ __forceinline__ float softplusf_(float x) {
    return (x > 20.f) ? x : log1pf(__expf(x));
}
__device__ __forceinline__ float f2tf_f(float x) {
    uint32_t r;
    asm("cvt.rna.tf32.f32 %0, %1;" : "=r"(r) : "f"(x));
    return __uint_as_float(r);
}
__device__ __forceinline__ void mma_tf32(float* d, const uint32_t* a, const uint32_t* b) {
    asm volatile(
        "mma.sync.aligned.m16n8k8.row.col.f32.tf32.tf32.f32 "
        "{%0,%1,%2,%3}, {%4,%5,%6,%7}, {%8,%9}, {%0,%1,%2,%3};"
        : "+f"(d[0]), "+f"(d[1]), "+f"(d[2]), "+f"(d[3])
        : "r"(a[0]), "r"(a[1]), "r"(a[2]), "r"(a[3]),
          "r"(b[0]), "r"(b[1]));
}

// ---------------- tf32 rounding copy (weights), float4 vectorized ----------------
__global__ void __launch_bounds__(256) round_tf32_kernel(
    const float* __restrict__ src, float* __restrict__ dst, int n4)
{
    int i = blockIdx.x * 256 + threadIdx.x;
    if (i < n4) {
        float4 v = reinterpret_cast<const float4*>(src)[i];
        v.x = f2tf_f(v.x); v.y = f2tf_f(v.y);
        v.z = f2tf_f(v.z); v.w = f2tf_f(v.w);
        reinterpret_cast<float4*>(dst)[i] = v;
    }
}

// ---------------- LayerNorm: one block per row of 1024, tf32-rounded output ----------------
__global__ void __launch_bounds__(256) ln_kernel(
    const float* __restrict__ x, const float* __restrict__ g,
    const float* __restrict__ b)
{
    int row = blockIdx.x;
    const float4* xr = reinterpret_cast<const float4*>(x + (size_t)row * DM);
    float4 v = xr[threadIdx.x];
    float s  = v.x + v.y + v.z + v.w;
    float ss = v.x*v.x + v.y*v.y + v.z*v.z + v.w*v.w;
    #pragma unroll
    for (int o = 16; o; o >>= 1) {
        s  += __shfl_xor_sync(0xffffffffu, s,  o);
        ss += __shfl_xor_sync(0xffffffffu, ss, o);
    }
    __shared__ float sh[8], sh2[8];
    int wid = threadIdx.x >> 5, lane = threadIdx.x & 31;
    if (lane == 0) { sh[wid] = s; sh2[wid] = ss; }
    __syncthreads();
    float S = 0.f, SS = 0.f;
    #pragma unroll
    for (int i = 0; i < 8; i++) { S += sh[i]; SS += sh2[i]; }
    float mu  = S * (1.f / DM);
    float var = SS * (1.f / DM) - mu * mu;
    float inv = rsqrtf(var + 1e-5f);
    const float4* gv4 = reinterpret_cast<const float4*>(g);
    const float4* bv4 = reinterpret_cast<const float4*>(b);
    float4 gv = gv4[threadIdx.x], bv = bv4[threadIdx.x];
    float4 o4;
    o4.x = f2tf_f((v.x - mu) * inv * gv.x + bv.x);
    o4.y = f2tf_f((v.y - mu) * inv * gv.y + bv.y);
    o4.z = f2tf_f((v.z - mu) * inv * gv.z + bv.z);
    o4.w = f2tf_f((v.w - mu) * inv * gv.w + bv.w);
    reinterpret_cast<float4*>(g_xn + (size_t)row * DM)[threadIdx.x] = o4;
}

// ---------------- tf32 tensor-core GEMM: C = act(A @ W^T + bias) (+resid) ----------------
// Operands MUST already be tf32-rounded in memory (no in-loop cvt).
// A [M, lda], W [N, K] row-major, C [M, ldc]. M = gridDim.y*128.
// K % 32 == 0. Block 128x128, Ktile 32, 3-stage cp.async pipeline, 2 CTA/SM.
// Smem tile [128][32] fp32, 16B-chunk XOR swizzle:
//   word(r, c) = r*32 + ((c>>2) ^ (r&7))*4 + (c&3)
#define STAGES 3
#define KT 32

__global__ void __launch_bounds__(256, 2) gemm_tc(
    const float* __restrict__ A, int lda,
    const float* __restrict__ W, int ldw,
    float* __restrict__ C, int ldc,
    int N, int K,
    const float* __restrict__ bias,
    const float* __restrict__ resid, int ldr,
    int act, int rndC)
{
    extern __shared__ float smbuf[];
    float* As = smbuf;                    // STAGES * 4096 floats
    float* Bs = smbuf + STAGES * 4096;

    const int tid  = threadIdx.x;
    const int wid  = tid >> 5, lane = tid & 31;
    const int g    = lane >> 2, t4 = lane & 3;
    const int wm   = wid & 3,  wn  = wid >> 2;    // 4(m) x 2(n) warps
    const int m0   = blockIdx.y * 128, n0 = blockIdx.x * 128;

    const int lr = tid >> 3;      // loader row 0..31
    const int lq = tid & 7;       // loader 16B chunk 0..7

    const float* Abase = A + (size_t)m0 * lda;

    auto load_tile = [&](int stage, int kt) {
        const int kbase = kt * KT + lq * 4;
        float* as = As + stage * 4096;
        float* bs = Bs + stage * 4096;
        #pragma unroll
        for (int i = 0; i < 4; i++) {
            int r = lr + i * 32;
            uint32_t so = (uint32_t)__cvta_generic_to_shared(
                &as[r * 32 + ((lq ^ (r & 7)) << 2)]);
            const float* gp = Abase + (size_t)r * lda + kbase;
            asm volatile("cp.async.cg.shared.global [%0], [%1], 16;\n"
                         :: "r"(so), "l"(gp));
        }
        #pragma unroll
        for (int i = 0; i < 4; i++) {
            int r = lr + i * 32;
            int nrow = n0 + r;
            uint32_t so = (uint32_t)__cvta_generic_to_shared(
                &bs[r * 32 + ((lq ^ (r & 7)) << 2)]);
            const float* gp = W + (size_t)nrow * ldw + kbase;
            int sz = (nrow < N) ? 16 : 0;   // zero-fill OOB rows
            asm volatile("cp.async.cg.shared.global [%0], [%1], 16, %2;\n"
                         :: "r"(so), "l"(gp), "r"(sz));
        }
    };

    float acc[2][8][4];
    #pragma unroll
    for (int mi = 0; mi < 2; mi++)
        #pragma unroll
        for (int ni = 0; ni < 8; ni++)
            #pragma unroll
            for (int j = 0; j < 4; j++) acc[mi][ni][j] = 0.f;

    const int ktiles = K / KT;

    #pragma unroll
    for (int s = 0; s < STAGES - 1; s++) {
        if (s < ktiles) load_tile(s, s);
        asm volatile("cp.async.commit_group;\n");
    }
    asm volatile("cp.async.wait_group %0;\n" :: "n"(STAGES - 2));
    __syncthreads();

    // per-lane invariant word offsets (row term folded; r&7 == g everywhere)
    const int aRow = (wm * 32 + g) * 32 + t4;   // + mi*512, +256 for row+8
    const int bRow = (wn * 64 + g) * 32 + t4;   // + ni*256

    for (int kt = 0; kt < ktiles; kt++) {
        int pre = kt + STAGES - 1;
        if (pre < ktiles) load_tile(pre % STAGES, pre);
        asm volatile("cp.async.commit_group;\n");

        const uint32_t* as = reinterpret_cast<const uint32_t*>(As + (kt % STAGES) * 4096);
        const uint32_t* bs = reinterpret_cast<const uint32_t*>(Bs + (kt % STAGES) * 4096);
        #pragma unroll
        for (int kk = 0; kk < 4; kk++) {
            const int x0 = ((kk * 2) ^ g) << 2;
            const int x1 = ((kk * 2 + 1) ^ g) << 2;
            uint32_t afr[2][4];
            #pragma unroll
            for (int mi = 0; mi < 2; mi++) {
                const uint32_t* ap = as + aRow + mi * 512;
                afr[mi][0] = ap[x0];
                afr[mi][1] = ap[256 + x0];
                afr[mi][2] = ap[x1];
                afr[mi][3] = ap[256 + x1];
            }
            #pragma unroll
            for (int ni = 0; ni < 8; ni++) {
                const uint32_t* bp = bs + bRow + ni * 256;
                uint32_t bfr[2];
                bfr[0] = bp[x0];
                bfr[1] = bp[x1];
                mma_tf32(acc[0][ni], afr[0], bfr);
                mma_tf32(acc[1][ni], afr[1], bfr);
            }
        }
        asm volatile("cp.async.wait_group %0;\n" :: "n"(STAGES - 2));
        __syncthreads();
    }

    // epilogue: c0=(g,2t4) c1=(g,2t4+1) c2=(g+8,2t4) c3=(g+8,2t4+1)
    #pragma unroll
    for (int mi = 0; mi < 2; mi++) {
        int m = m0 + wm * 32 + mi * 16 + g;
        #pragma unroll
        for (int ni = 0; ni < 8; ni++) {
            int n = n0 + wn * 64 + ni * 8 + t4 * 2;
            if (n < N) {
                float v00 = acc[mi][ni][0], v01 = acc[mi][ni][1];
                float v10 = acc[mi][ni][2], v11 = acc[mi][ni][3];
                if (bias) {
                    float b0 = bias[n], b1 = bias[n + 1];
                    v00 += b0; v01 += b1; v10 += b0; v11 += b1;
                }
                if (act == 1) {
                    v00 = softplusf_(v00); v01 = softplusf_(v01);
                    v10 = softplusf_(v10); v11 = softplusf_(v11);
                }
                if (resid) {
                    v00 += resid[(size_t)m * ldr + n];
                    v01 += resid[(size_t)m * ldr + n + 1];
                    v10 += resid[(size_t)(m + 8) * ldr + n];
                    v11 += resid[(size_t)(m + 8) * ldr + n + 1];
                }
                if (rndC) {
                    v00 = f2tf_f(v00); v01 = f2tf_f(v01);
                    v10 = f2tf_f(v10); v11 = f2tf_f(v11);
                }
                *reinterpret_cast<float2*>(&C[(size_t)m * ldc + n]) =
                    make_float2(v00, v01);
                *reinterpret_cast<float2*>(&C[(size_t)(m + 8) * ldc + n]) =
                    make_float2(v10, v11);
            }
        }
    }
}

// ---------------- depthwise causal conv (len 4) + silu, tf32-rounded output ----------------
__global__ void conv_silu_kernel(const float* __restrict__ cw,
                                 const float* __restrict__ cb, int dir)
{
    int idx = blockIdx.x * 256 + threadIdx.x;      // over BL*DI
    int d = idx & (DI - 1);
    int t = (idx >> 11) & (LL - 1);
    int b = idx >> 22;
    float acc = cb[d];
    #pragma unroll
    for (int j = 0; j < 4; j++) {
        int tt = dir ? (t + 3 - j) : (t - 3 + j);
        if ((unsigned)tt < LL)
            acc += cw[d * 4 + j] * g_xz[(size_t)((b << 11) + tt) * (2 * DI) + d];
    }
    g_xi[idx] = f2tf_f(acc * sigmoidf_(acc));
}

// ---------------- selective scan ----------------
#define SCAN_TC 64
__global__ void __launch_bounds__(128) scan_kernel(
    const float* __restrict__ A_log, const float* __restrict__ Dvec, int dir)
{
    __shared__ float sBC[SCAN_TC][32];   // [t][0..15]=B, [16..31]=C

    const int lane = threadIdx.x & 31;
    const int warp = threadIdx.x >> 5;
    const int sgrp = lane & 3;
    const int d = blockIdx.x * 32 + warp * 8 + (lane >> 2);
    const int b = blockIdx.y;
    const int rowbase = b * LL;

    float Aarr[4];
    #pragma unroll
    for (int i = 0; i < 4; i++)
        Aarr[i] = -__expf(A_log[d * DS + sgrp * 4 + i]);
    const float Dd = Dvec[d];

    float h[4] = {0.f, 0.f, 0.f, 0.f};

    for (int tc = 0; tc < LL; tc += SCAN_TC) {
        __syncthreads();
        for (int k = threadIdx.x; k < SCAN_TC * 32; k += 128) {
            int t = k >> 5, c = k & 31;
            int ts = tc + t;
            int o = dir ? (LL - 1 - ts) : ts;
            sBC[t][c] = g_proj[(size_t)(rowbase + o) * NP + 64 + c];
        }
        __syncthreads();

        for (int t = 0; t < SCAN_TC; t++) {
            int ts = tc + t;
            int o = dir ? (LL - 1 - ts) : ts;
            size_t row = (size_t)(rowbase + o);
            float dlt = g_delta[row * DI + d];
            float u   = g_xi[row * DI + d];
            float du  = dlt * u;
            float y = 0.f;
            #pragma unroll
            for (int i = 0; i < 4; i++) {
                int s = sgrp * 4 + i;
                float a = __expf(dlt * Aarr[i]);
                h[i] = a * h[i] + du * sBC[t][s];
                y += h[i] * sBC[t][16 + s];
            }
            y += __shfl_xor_sync(0xffffffffu, y, 1);
            y += __shfl_xor_sync(0xffffffffu, y, 2);
            if (sgrp == 0) {
                float z = g_xz[row * (2 * DI) + DI + d];
                g_ycore[row * DI + d] =
                    f2tf_f((y + u * Dd) * z * sigmoidf_(z));
            }
        }
    }
}

// ---------------- launch ----------------
extern "C" void kernel_launch(void* const* d_in, const int* in_sizes, int n_in,
                              void* d_out, int out_size)
{
    (void)in_sizes; (void)n_in; (void)out_size;

    const float* x       = (const float*)d_in[0];
    const float* ln_g    = (const float*)d_in[1];
    const float* ln_b    = (const float*)d_in[2];
    const float* merge_w = (const float*)d_in[3];
    const float* merge_b = (const float*)d_in[4];

    float *p_xn, *p_xz, *p_xi, *p_proj, *p_delta, *p_ycore, *p_ycat;
    float *p_win, *p_wxp, *p_wdt, *p_wout, *p_wmg;
    cudaGetSymbolAddress((void**)&p_xn,    g_xn);
    cudaGetSymbolAddress((void**)&p_xz,    g_xz);
    cudaGetSymbolAddress((void**)&p_xi,    g_xi);
    cudaGetSymbolAddress((void**)&p_proj,  g_proj);
    cudaGetSymbolAddress((void**)&p_delta, g_delta);
    cudaGetSymbolAddress((void**)&p_ycore, g_ycore);
    cudaGetSymbolAddress((void**)&p_ycat,  g_ycat);
    cudaGetSymbolAddress((void**)&p_win,   w_in);
    cudaGetSymbolAddress((void**)&p_wxp,   w_xp);
    cudaGetSymbolAddress((void**)&p_wdt,   w_dt);
    cudaGetSymbolAddress((void**)&p_wout,  w_out);
    cudaGetSymbolAddress((void**)&p_wmg,   w_mg);

    const int smem = STAGES * 2 * 4096 * sizeof(float);   // 96 KB
    cudaFuncSetAttribute(gemm_tc, cudaFuncAttributeMaxDynamicSharedMemorySize, smem);

    auto rnd = [](const float* s, float* d, int n) {
        round_tf32_kernel<<<(n / 4 + 255) / 256, 256>>>(s, d, n / 4);
    };

    ln_kernel<<<BL, 256>>>(x, ln_g, ln_b);
    rnd(merge_w, p_wmg, DM * 2 * DM);

    for (int dir = 0; dir < 2; dir++) {
        int base = 5 + dir * 9;
        const float* in_w    = (const float*)d_in[base + 0];
        const float* conv_w  = (const float*)d_in[base + 1];
        const float* conv_b  = (const float*)d_in[base + 2];
        const float* xproj_w = (const float*)d_in[base + 3];
        const float* dt_w    = (const float*)d_in[base + 4];
        const float* dt_b    = (const float*)d_in[base + 5];
        const float* A_log   = (const float*)d_in[base + 6];
        const float* Dv      = (const float*)d_in[base + 7];
        const float* out_w   = (const float*)d_in[base + 8];

        rnd(in_w,    p_win,  2 * DI * DM);
        rnd(xproj_w, p_wxp,  NP * DI);
        rnd(dt_w,    p_wdt,  DI * DTR);
        rnd(out_w,   p_wout, DM * DI);

        // xz = xn @ in_w^T   [8192,1024] x [4096,1024]^T
        gemm_tc<<<dim3(2 * DI / 128, BL / 128), 256, smem>>>(
            p_xn, DM, p_win, DM, p_xz, 2 * DI, 2 * DI, DM,
            nullptr, nullptr, 0, 0, 0);

        // xi = silu(causal_conv(xz[:, :DI]))  (tf32-rounded)
        conv_silu_kernel<<<(BL * DI) / 256, 256>>>(conv_w, conv_b, dir);

        // proj = xi @ xproj_w^T  (tf32-rounded output; feeds dt GEMM + scan)
        gemm_tc<<<dim3(1, BL / 128), 256, smem>>>(
            p_xi, DI, p_wxp, DI, p_proj, NP, NP, DI,
            nullptr, nullptr, 0, 0, 1);

        // delta = softplus(proj[:, :64] @ dt_w^T + dt_b)
        gemm_tc<<<dim3(DI / 128, BL / 128), 256, smem>>>(
            p_proj, NP, p_wdt, DTR, p_delta, DI, DI, DTR,
            dt_b, nullptr, 0, 1, 0);

        // selective scan -> ycore (gated by silu(z), tf32-rounded)
        scan_kernel<<<dim3(DI / 32, BB), 128>>>(A_log, Dv, dir);

        // y_dir = ycore @ out_w^T into ycat[:, dir*DM:]  (tf32-rounded)
        gemm_tc<<<dim3(DM / 128, BL / 128), 256, smem>>>(
            p_ycore, DI, p_wout, DI, p_ycat + dir * DM, 2 * DM, DM, DI,
            nullptr, nullptr, 0, 0, 1);
    }

    // out = x + ycat @ merge_w^T + merge_b  (full fp32 output)
    gemm_tc<<<dim3(DM / 128, BL / 128), 256, smem>>>(
        p_ycat, 2 * DM, p_wmg, 2 * DM, (float*)d_out, DM, DM, 2 * DM,
        merge_b, x, DM, 0, 0);
}

// round 7
// speedup vs baseline: 2.1617x; 1.1647x over previous
#include <cuda_runtime.h>
#include <cuda_bf16.h>
#include <cstdint>

// ---------------- problem constants ----------------
#define BB   4
#define LL   2048
#define DM   1024
#define DI   2048      // d_inner
#define DS   16        // d_state
#define DTR  64        // dt_rank
#define NP   96        // dt_rank + 2*d_state
#define BL   (BB*LL)   // 8192 rows

typedef __nv_bfloat16 bf16;

// ---------------- scratch (static device globals; no runtime alloc) ----------------
__device__ bf16 g_xn   [BL*DM];
__device__ bf16 g_xz   [(size_t)BL*2*DI];
__device__ bf16 g_xi   [(size_t)BL*DI];
__device__ bf16 g_proj [BL*NP];
__device__ bf16 g_delta[(size_t)BL*DI];
__device__ bf16 g_ycore[(size_t)BL*DI];
__device__ bf16 g_ycat [(size_t)BL*2*DM];
// bf16 weight copies
__device__ bf16 w_in [2*DI*DM];
__device__ bf16 w_xp [NP*DI];
__device__ bf16 w_dt [DI*DTR];
__device__ bf16 w_out[DM*DI];
__device__ bf16 w_mg [DM*2*DM];

// ---------------- helpers ----------------
__device__ __forceinline__ float sigmoidf_(float x) {
    return 1.f / (1.f + __expf(-x));
}
__device__ __forceinline__ float softplusf_(float x) {
    return (x > 20.f) ? x : log1pf(__expf(x));
}
__device__ __forceinline__ uint32_t smem_u32(const void* p) {
    uint32_t a;
    asm("{ .reg .u64 t; cvta.to.shared.u64 t, %1; cvt.u32.u64 %0, t; }"
        : "=r"(a) : "l"(p));
    return a;
}
__device__ __forceinline__ void ldsm4(uint32_t* r, uint32_t addr) {
    asm volatile("ldmatrix.sync.aligned.m8n8.x4.shared.b16 {%0,%1,%2,%3}, [%4];"
                 : "=r"(r[0]), "=r"(r[1]), "=r"(r[2]), "=r"(r[3]) : "r"(addr));
}
__device__ __forceinline__ void mma_bf16(float* d, const uint32_t* a, const uint32_t* b) {
    asm volatile(
        "mma.sync.aligned.m16n8k16.row.col.f32.bf16.bf16.f32 "
        "{%0,%1,%2,%3}, {%4,%5,%6,%7}, {%8,%9}, {%0,%1,%2,%3};"
        : "+f"(d[0]), "+f"(d[1]), "+f"(d[2]), "+f"(d[3])
        : "r"(a[0]), "r"(a[1]), "r"(a[2]), "r"(a[3]),
          "r"(b[0]), "r"(b[1]));
}

// ---------------- f32 -> bf16 conversion copy (weights) ----------------
__global__ void __launch_bounds__(256) f2bf_kernel(
    const float* __restrict__ src, bf16* __restrict__ dst, int n4)
{
    int i = blockIdx.x * 256 + threadIdx.x;
    if (i < n4) {
        float4 v = reinterpret_cast<const float4*>(src)[i];
        __nv_bfloat162 a = __floats2bfloat162_rn(v.x, v.y);
        __nv_bfloat162 b = __floats2bfloat162_rn(v.z, v.w);
        reinterpret_cast<__nv_bfloat162*>(dst)[i * 2]     = a;
        reinterpret_cast<__nv_bfloat162*>(dst)[i * 2 + 1] = b;
    }
}

// ---------------- LayerNorm: one block per row of 1024, bf16 output ----------------
__global__ void __launch_bounds__(256) ln_kernel(
    const float* __restrict__ x, const float* __restrict__ g,
    const float* __restrict__ b)
{
    int row = blockIdx.x;
    const float4* xr = reinterpret_cast<const float4*>(x + (size_t)row * DM);
    float4 v = xr[threadIdx.x];
    float s  = v.x + v.y + v.z + v.w;
    float ss = v.x*v.x + v.y*v.y + v.z*v.z + v.w*v.w;
    #pragma unroll
    for (int o = 16; o; o >>= 1) {
        s  += __shfl_xor_sync(0xffffffffu, s,  o);
        ss += __shfl_xor_sync(0xffffffffu, ss, o);
    }
    __shared__ float sh[8], sh2[8];
    int wid = threadIdx.x >> 5, lane = threadIdx.x & 31;
    if (lane == 0) { sh[wid] = s; sh2[wid] = ss; }
    __syncthreads();
    float S = 0.f, SS = 0.f;
    #pragma unroll
    for (int i = 0; i < 8; i++) { S += sh[i]; SS += sh2[i]; }
    float mu  = S * (1.f / DM);
    float var = SS * (1.f / DM) - mu * mu;
    float inv = rsqrtf(var + 1e-5f);
    const float4* gv4 = reinterpret_cast<const float4*>(g);
    const float4* bv4 = reinterpret_cast<const float4*>(b);
    float4 gv = gv4[threadIdx.x], bv = bv4[threadIdx.x];
    __nv_bfloat162 o0 = __floats2bfloat162_rn(
        (v.x - mu) * inv * gv.x + bv.x, (v.y - mu) * inv * gv.y + bv.y);
    __nv_bfloat162 o1 = __floats2bfloat162_rn(
        (v.z - mu) * inv * gv.z + bv.z, (v.w - mu) * inv * gv.w + bv.w);
    __nv_bfloat162* dst =
        reinterpret_cast<__nv_bfloat162*>(g_xn + (size_t)row * DM);
    dst[threadIdx.x * 2]     = o0;
    dst[threadIdx.x * 2 + 1] = o1;
}

// =====================================================================
// bf16 tensor-core GEMM: C = act(A @ W^T + bias) (+resid)
// A [M, lda] bf16, W [N, ldw] bf16 (row-major, K contiguous).
// Tile 128x128, K-tile 64 bf16 (128 B/row, SW128 swizzle), 3-stage cp.async.
// 256 threads (8 warps: 4m x 2n, warp tile 32x64), 2 CTAs/SM.
// mma m16n8k16 fed by ldmatrix.x4.
// Smem chunk addr: row*128 + ((chunk ^ (row&7)) * 16), chunk = byte/16.
// =====================================================================
#define BKT  64
#define STG  3
#define STG_BYTES 32768          // 16 KB A + 16 KB B
#define GSMEM (STG * STG_BYTES)  // 96 KB

__global__ void __launch_bounds__(256, 2) gemm_bf(
    const bf16* __restrict__ A, int lda,
    const bf16* __restrict__ W, int ldw,
    void* __restrict__ Cv, int ldc,
    int N, int K,
    const float* __restrict__ bias,
    const float* __restrict__ resid, int ldr,
    int act, int outF32)
{
    extern __shared__ char smraw[];
    const uint32_t sb0 = smem_u32(smraw);

    const int tid  = threadIdx.x;
    const int wid  = tid >> 5, lane = tid & 31;
    const int g    = lane >> 2, tg = lane & 3;
    const int wm   = wid & 3,  wn  = wid >> 2;
    const int m0   = blockIdx.y * 128, n0 = blockIdx.x * 128;

    // loader: thread -> row (tid>>1), 4 chunks starting at (tid&1)*4
    const int lr  = tid >> 1;
    const int lcb = (tid & 1) * 4;
    const int lnrow = n0 + lr;
    const bf16* agr = A + (size_t)(m0 + lr) * lda + lcb * 8;
    const bf16* wgr = W + (size_t)lnrow * ldw + lcb * 8;
    const int wsz = (lnrow < N) ? 16 : 0;

    auto load_tile = [&](int stage, int kt) {
        uint32_t ab = sb0 + stage * STG_BYTES + lr * 128;
        uint32_t bb = ab + 16384;
        const bf16* ag = agr + kt * BKT;
        const bf16* wg = wgr + kt * BKT;
        #pragma unroll
        for (int j = 0; j < 4; j++) {
            uint32_t off = (uint32_t)(((lcb + j) ^ (lr & 7)) << 4);
            asm volatile("cp.async.cg.shared.global [%0], [%1], 16;\n"
                         :: "r"(ab + off), "l"(ag + j * 8));
            asm volatile("cp.async.cg.shared.global [%0], [%1], 16, %2;\n"
                         :: "r"(bb + off), "l"(wg + j * 8), "r"(wsz));
        }
    };

    float acc[2][8][4];
    #pragma unroll
    for (int mi = 0; mi < 2; mi++)
        #pragma unroll
        for (int ni = 0; ni < 8; ni++)
            #pragma unroll
            for (int j = 0; j < 4; j++) acc[mi][ni][j] = 0.f;

    const int ktiles = K / BKT;

    #pragma unroll
    for (int s = 0; s < STG - 1; s++) {
        if (s < ktiles) load_tile(s, s);
        asm volatile("cp.async.commit_group;\n");
    }
    asm volatile("cp.async.wait_group %0;\n" :: "n"(STG - 2));
    __syncthreads();

    // ldmatrix per-lane address components
    // A: lanes 0-7: rows 0-7 klo | 8-15: rows 8-15 klo | 16-23: rows 0-7 khi | 24-31: rows 8-15 khi
    const int aRowL  = wm * 32 + (lane & 15);        // + mi*16
    const int aKhalf = (lane >> 4) & 1;
    const int aSwz   = lane & 7;                      // == row&7 (mi*16 keeps low3)
    // B: matrix idx m = lane>>3: ni_local = m>>1, khalf = m&1, row = wn*64 + jgrp*16 + ni_local*8 + (lane&7)
    const int bNloc  = ((lane >> 4) & 1);            // m>>1
    const int bKhalf = (lane >> 3) & 1;              // m&1
    const int bRowBase = wn * 64 + bNloc * 8 + (lane & 7);
    const int bSwz   = lane & 7;

    for (int kt = 0; kt < ktiles; kt++) {
        int pre = kt + STG - 1;
        if (pre < ktiles) load_tile(pre % STG, pre);
        asm volatile("cp.async.commit_group;\n");

        const uint32_t abase = sb0 + (kt % STG) * STG_BYTES;
        const uint32_t bbase = abase + 16384;

        #pragma unroll
        for (int kk = 0; kk < 4; kk++) {
            uint32_t af[2][4];
            #pragma unroll
            for (int mi = 0; mi < 2; mi++) {
                uint32_t addr = abase + (uint32_t)(aRowL + mi * 16) * 128
                              + (uint32_t)(((kk * 2 + aKhalf) ^ aSwz) << 4);
                ldsm4(af[mi], addr);
            }
            uint32_t bf[8][2];
            #pragma unroll
            for (int j = 0; j < 4; j++) {
                uint32_t addr = bbase + (uint32_t)(bRowBase + j * 16) * 128
                              + (uint32_t)(((kk * 2 + bKhalf) ^ bSwz) << 4);
                uint32_t t[4];
                ldsm4(t, addr);
                bf[2*j][0] = t[0]; bf[2*j][1] = t[1];
                bf[2*j+1][0] = t[2]; bf[2*j+1][1] = t[3];
            }
            #pragma unroll
            for (int ni = 0; ni < 8; ni++) {
                mma_bf16(acc[0][ni], af[0], bf[ni]);
                mma_bf16(acc[1][ni], af[1], bf[ni]);
            }
        }
        asm volatile("cp.async.wait_group %0;\n" :: "n"(STG - 2));
        __syncthreads();
    }

    // epilogue: c0=(g,2tg) c1=(g,2tg+1) c2=(g+8,2tg) c3=(g+8,2tg+1)
    #pragma unroll
    for (int mi = 0; mi < 2; mi++) {
        int m = m0 + wm * 32 + mi * 16 + g;
        #pragma unroll
        for (int ni = 0; ni < 8; ni++) {
            int n = n0 + wn * 64 + ni * 8 + tg * 2;
            if (n < N) {
                float v00 = acc[mi][ni][0], v01 = acc[mi][ni][1];
                float v10 = acc[mi][ni][2], v11 = acc[mi][ni][3];
                if (bias) {
                    float b0 = bias[n], b1 = bias[n + 1];
                    v00 += b0; v01 += b1; v10 += b0; v11 += b1;
                }
                if (act == 1) {
                    v00 = softplusf_(v00); v01 = softplusf_(v01);
                    v10 = softplusf_(v10); v11 = softplusf_(v11);
                }
                if (resid) {
                    v00 += resid[(size_t)m * ldr + n];
                    v01 += resid[(size_t)m * ldr + n + 1];
                    v10 += resid[(size_t)(m + 8) * ldr + n];
                    v11 += resid[(size_t)(m + 8) * ldr + n + 1];
                }
                if (outF32) {
                    float* C = (float*)Cv;
                    *reinterpret_cast<float2*>(&C[(size_t)m * ldc + n]) =
                        make_float2(v00, v01);
                    *reinterpret_cast<float2*>(&C[(size_t)(m + 8) * ldc + n]) =
                        make_float2(v10, v11);
                } else {
                    bf16* C = (bf16*)Cv;
                    *reinterpret_cast<__nv_bfloat162*>(&C[(size_t)m * ldc + n]) =
                        __floats2bfloat162_rn(v00, v01);
                    *reinterpret_cast<__nv_bfloat162*>(&C[(size_t)(m + 8) * ldc + n]) =
                        __floats2bfloat162_rn(v10, v11);
                }
            }
        }
    }
}

// ---------------- depthwise causal conv (len 4) + silu (bf16 in/out) ----------------
__global__ void conv_silu_kernel(const float* __restrict__ cw,
                                 const float* __restrict__ cb, int dir)
{
    int idx = blockIdx.x * 256 + threadIdx.x;
    int d = idx & (DI - 1);
    int t = (idx >> 11) & (LL - 1);
    int b = idx >> 22;
    float acc = cb[d];
    #pragma unroll
    for (int j = 0; j < 4; j++) {
        int tt = dir ? (t + 3 - j) : (t - 3 + j);
        if ((unsigned)tt < LL)
            acc += cw[d * 4 + j] *
                   __bfloat162float(g_xz[(size_t)((b << 11) + tt) * (2 * DI) + d]);
    }
    g_xi[idx] = __float2bfloat16_rn(acc * sigmoidf_(acc));
}

// ---------------- selective scan (bf16 inputs, fp32 state) ----------------
#define SCAN_TC 64
__global__ void __launch_bounds__(128) scan_kernel(
    const float* __restrict__ A_log, const float* __restrict__ Dvec, int dir)
{
    __shared__ float sBC[SCAN_TC][32];

    const int lane = threadIdx.x & 31;
    const int warp = threadIdx.x >> 5;
    const int sgrp = lane & 3;
    const int d = blockIdx.x * 32 + warp * 8 + (lane >> 2);
    const int b = blockIdx.y;
    const int rowbase = b * LL;

    float Aarr[4];
    #pragma unroll
    for (int i = 0; i < 4; i++)
        Aarr[i] = -__expf(A_log[d * DS + sgrp * 4 + i]);
    const float Dd = Dvec[d];

    float h[4] = {0.f, 0.f, 0.f, 0.f};

    for (int tc = 0; tc < LL; tc += SCAN_TC) {
        __syncthreads();
        for (int k = threadIdx.x; k < SCAN_TC * 32; k += 128) {
            int t = k >> 5, c = k & 31;
            int ts = tc + t;
            int o = dir ? (LL - 1 - ts) : ts;
            sBC[t][c] =
                __bfloat162float(g_proj[(size_t)(rowbase + o) * NP + 64 + c]);
        }
        __syncthreads();

        for (int t = 0; t < SCAN_TC; t++) {
            int ts = tc + t;
            int o = dir ? (LL - 1 - ts) : ts;
            size_t row = (size_t)(rowbase + o);
            float dlt = __bfloat162float(g_delta[row * DI + d]);
            float u   = __bfloat162float(g_xi[row * DI + d]);
            float du  = dlt * u;
            float y = 0.f;
            #pragma unroll
            for (int i = 0; i < 4; i++) {
                int s = sgrp * 4 + i;
                float a = __expf(dlt * Aarr[i]);
                h[i] = a * h[i] + du * sBC[t][s];
                y += h[i] * sBC[t][16 + s];
            }
            y += __shfl_xor_sync(0xffffffffu, y, 1);
            y += __shfl_xor_sync(0xffffffffu, y, 2);
            if (sgrp == 0) {
                float z = __bfloat162float(g_xz[row * (2 * DI) + DI + d]);
                g_ycore[row * DI + d] =
                    __float2bfloat16_rn((y + u * Dd) * z * sigmoidf_(z));
            }
        }
    }
}

// ---------------- launch ----------------
extern "C" void kernel_launch(void* const* d_in, const int* in_sizes, int n_in,
                              void* d_out, int out_size)
{
    (void)in_sizes; (void)n_in; (void)out_size;

    const float* x       = (const float*)d_in[0];
    const float* ln_g    = (const float*)d_in[1];
    const float* ln_b    = (const float*)d_in[2];
    const float* merge_w = (const float*)d_in[3];
    const float* merge_b = (const float*)d_in[4];

    bf16 *p_xn, *p_xz, *p_xi, *p_proj, *p_delta, *p_ycore, *p_ycat;
    bf16 *p_win, *p_wxp, *p_wdt, *p_wout, *p_wmg;
    cudaGetSymbolAddress((void**)&p_xn,    g_xn);
    cudaGetSymbolAddress((void**)&p_xz,    g_xz);
    cudaGetSymbolAddress((void**)&p_xi,    g_xi);
    cudaGetSymbolAddress((void**)&p_proj,  g_proj);
    cudaGetSymbolAddress((void**)&p_delta, g_delta);
    cudaGetSymbolAddress((void**)&p_ycore, g_ycore);
    cudaGetSymbolAddress((void**)&p_ycat,  g_ycat);
    cudaGetSymbolAddress((void**)&p_win,   w_in);
    cudaGetSymbolAddress((void**)&p_wxp,   w_xp);
    cudaGetSymbolAddress((void**)&p_wdt,   w_dt);
    cudaGetSymbolAddress((void**)&p_wout,  w_out);
    cudaGetSymbolAddress((void**)&p_wmg,   w_mg);

    cudaFuncSetAttribute(gemm_bf, cudaFuncAttributeMaxDynamicSharedMemorySize,
                         GSMEM);

    auto cvt = [](const float* s, bf16* d, int n) {
        f2bf_kernel<<<(n / 4 + 255) / 256, 256>>>(s, d, n / 4);
    };

    ln_kernel<<<BL, 256>>>(x, ln_g, ln_b);
    cvt(merge_w, p_wmg, DM * 2 * DM);

    for (int dir = 0; dir < 2; dir++) {
        int base = 5 + dir * 9;
        const float* in_w    = (const float*)d_in[base + 0];
        const float* conv_w  = (const float*)d_in[base + 1];
        const float* conv_b  = (const float*)d_in[base + 2];
        const float* xproj_w = (const float*)d_in[base + 3];
        const float* dt_w    = (const float*)d_in[base + 4];
        const float* dt_b    = (const float*)d_in[base + 5];
        const float* A_log   = (const float*)d_in[base + 6];
        const float* Dv      = (const float*)d_in[base + 7];
        const float* out_w   = (const float*)d_in[base + 8];

        cvt(in_w,    p_win,  2 * DI * DM);
        cvt(xproj_w, p_wxp,  NP * DI);
        cvt(dt_w,    p_wdt,  DI * DTR);
        cvt(out_w,   p_wout, DM * DI);

        // xz = xn @ in_w^T   [8192,1024] x [4096,1024]^T
        gemm_bf<<<dim3(2 * DI / 128, BL / 128), 256, GSMEM>>>(
            p_xn, DM, p_win, DM, p_xz, 2 * DI, 2 * DI, DM,
            nullptr, nullptr, 0, 0, 0);

        // xi = silu(causal_conv(xz[:, :DI]))
        conv_silu_kernel<<<(BL * DI) / 256, 256>>>(conv_w, conv_b, dir);

        // proj = xi @ xproj_w^T   (N=96, zero-filled OOB rows + store guard)
        gemm_bf<<<dim3(1, BL / 128), 256, GSMEM>>>(
            p_xi, DI, p_wxp, DI, p_proj, NP, NP, DI,
            nullptr, nullptr, 0, 0, 0);

        // delta = softplus(proj[:, :64] @ dt_w^T + dt_b)   (K=64)
        gemm_bf<<<dim3(DI / 128, BL / 128), 256, GSMEM>>>(
            p_proj, NP, p_wdt, DTR, p_delta, DI, DI, DTR,
            dt_b, nullptr, 0, 1, 0);

        // selective scan -> ycore (gated by silu(z))
        scan_kernel<<<dim3(DI / 32, BB), 128>>>(A_log, Dv, dir);

        // y_dir = ycore @ out_w^T into ycat[:, dir*DM:]
        gemm_bf<<<dim3(DM / 128, BL / 128), 256, GSMEM>>>(
            p_ycore, DI, p_wout, DI, p_ycat + dir * DM, 2 * DM, DM, DI,
            nullptr, nullptr, 0, 0, 0);
    }

    // out = x + ycat @ merge_w^T + merge_b   (fp32 out + residual)
    gemm_bf<<<dim3(DM / 128, BL / 128), 256, GSMEM>>>(
        p_ycat, 2 * DM, p_wmg, 2 * DM, d_out, DM, DM, 2 * DM,
        merge_b, x, DM, 0, 1);
}